// round 11
// baseline (speedup 1.0000x reference)
#include <cuda_runtime.h>
#include <math.h>

// Shape fixed by dataset: (N=32, C=1, H=1024, W=1024) f32.
#define HDIM 1024
#define WDIM 1024
#define W4   (WDIM / 4)        // 256 float4 per row
#define C4   4                 // float4-columns per block
#define CB   (C4 * 4)          // 16 scalar columns per block
#define NWORDS (HDIM / 32)     // 32 words per column
#define NTHREADS 128
#define MAXBLK 2048

__device__ unsigned long long g_pen;
__device__ unsigned long long g_cnt;
__device__ float              g_bce[MAXBLK];
__device__ unsigned int       g_done;

__global__ __launch_bounds__(NTHREADS, 12)
void dtl_main(const float* __restrict__ pred, const float* __restrict__ targ,
              float* __restrict__ out) {
    __shared__ unsigned int mask[NWORDS][CB + 1];   // [word][col]
    __shared__ float        s_bce[NTHREADS];
    __shared__ unsigned int s_pen[NTHREADS];
    __shared__ unsigned int s_cnt[NTHREADS];
    __shared__ bool         s_last;

    const int tid = threadIdx.x;
    const int c   = tid & (C4 - 1);      // float4 column 0..3
    const int r   = tid >> 2;            // word index 0..31
    const int n   = blockIdx.y;
    const int cb  = c * 4;
    const int i0  = r * 32;

    const float4* t4 = (const float4*)(targ + (size_t)n * HDIM * WDIM)
                       + blockIdx.x * C4 + c;
    const float4* p4 = (const float4*)(pred + (size_t)n * HDIM * WDIM)
                       + blockIdx.x * C4 + c;

    // ---- Phase 1: build mask words via exact FFMA bit-packing ----
    {
        float lo0 = 0.f, lo1 = 0.f, lo2 = 0.f, lo3 = 0.f;
        float hi0 = 0.f, hi1 = 0.f, hi2 = 0.f, hi3 = 0.f;
        const float4* tp = t4 + (size_t)i0 * W4;
        #pragma unroll
        for (int b = 0; b < 16; ++b) {
            float4 t = __ldcs(tp); tp += W4;
            const float s = (float)(1u << b);
            lo0 += t.x * s; lo1 += t.y * s; lo2 += t.z * s; lo3 += t.w * s;
        }
        #pragma unroll
        for (int b = 0; b < 16; ++b) {
            float4 t = __ldcs(tp); tp += W4;
            const float s = (float)(1u << b);
            hi0 += t.x * s; hi1 += t.y * s; hi2 += t.z * s; hi3 += t.w * s;
        }
        mask[r][cb + 0] = (unsigned)lo0 | ((unsigned)hi0 << 16);
        mask[r][cb + 1] = (unsigned)lo1 | ((unsigned)hi1 << 16);
        mask[r][cb + 2] = (unsigned)lo2 | ((unsigned)hi2 << 16);
        mask[r][cb + 3] = (unsigned)lo3 | ((unsigned)hi3 << 16);
    }
    __syncthreads();

    // ---- Per-column boundary state (once per thread) ----
    unsigned mw[4];
    int prev[4], next[4], nextAfter[4];
    #pragma unroll
    for (int j = 0; j < 4; ++j) {
        mw[j] = mask[r][cb + j];
        int p = -(1 << 20);
        for (int wd = r - 1; wd >= 0; --wd) {
            unsigned m = mask[wd][cb + j];
            if (m) { p = wd * 32 + 31 - __clz(m); break; }
        }
        prev[j] = p;
        int na = 1 << 20;
        for (int wd = r + 1; wd < NWORDS; ++wd) {
            unsigned m = mask[wd][cb + j];
            if (m) { na = wd * 32 + __ffs(m) - 1; break; }
        }
        nextAfter[j] = na;
        next[j] = mw[j] ? i0 + __ffs(mw[j]) - 1 : na;
    }

    // ---- Phase 2: stream predictions, accumulate ----
    float bce = 0.0f;
    unsigned int pc = 0;                 // (pen << 8) | cnt packed accumulator
    {
        const float4* pp = p4 + (size_t)i0 * W4;
        #pragma unroll 8
        for (int b = 0; b < 32; ++b) {
            const int i = i0 + b;
            float4 p = __ldcs(pp); pp += W4;
            const float pv[4] = {p.x, p.y, p.z, p.w};
            float e[4];
            #pragma unroll
            for (int j = 0; j < 4; ++j) {
                const float v = pv[j];
                const unsigned bit = (mw[j] >> b) & 1u;
                if (bit) {
                    prev[j] = i;
                    const unsigned r2 = mw[j] & (0xFFFFFFFEu << b);
                    next[j] = r2 ? i0 + __ffs(r2) - 1 : nextAfter[j];
                    bce -= v;
                } else {
                    const int dist = min(min(i - prev[j], next[j] - i), HDIM);
                    if (v > 0.0f) pc += ((unsigned)dist << 8) + 1u;
                }
                bce += fmaxf(v, 0.0f);
                e[j] = __expf(-fabsf(v));
            }
            // log batching: product of (1+e_j) in (1,16] -> one LG2
            bce += __logf(((1.0f + e[0]) * (1.0f + e[1]))
                        * ((1.0f + e[2]) * (1.0f + e[3])));
        }
    }

    // ---- Block reduction (deterministic tree) ----
    s_bce[tid] = bce; s_pen[tid] = pc >> 8; s_cnt[tid] = pc & 0xFFu;
    __syncthreads();
    for (int s = NTHREADS / 2; s > 0; s >>= 1) {
        if (tid < s) {
            s_bce[tid] += s_bce[tid + s];
            s_pen[tid] += s_pen[tid + s];
            s_cnt[tid] += s_cnt[tid + s];
        }
        __syncthreads();
    }

    const int nblk = gridDim.x * gridDim.y;
    if (tid == 0) {
        const int blk = blockIdx.y * gridDim.x + blockIdx.x;
        g_bce[blk] = s_bce[0];
        atomicAdd(&g_pen, (unsigned long long)s_pen[0]);
        atomicAdd(&g_cnt, (unsigned long long)s_cnt[0]);
        __threadfence();
        unsigned int ticket = atomicAdd(&g_done, 1u);
        s_last = (ticket == (unsigned)(nblk - 1));
    }
    __syncthreads();

    // ---- Last block finalizes (fixed-order sums -> deterministic) ----
    if (s_last) {
        __threadfence();
        float acc = 0.0f;
        for (int i = tid; i < nblk; i += NTHREADS) acc += g_bce[i];
        s_bce[tid] = acc;
        __syncthreads();
        for (int s = NTHREADS / 2; s > 0; s >>= 1) {
            if (tid < s) s_bce[tid] += s_bce[tid + s];
            __syncthreads();
        }
        if (tid == 0) {
            const double count = (double)gridDim.y * HDIM * WDIM;
            const double bce_mean = (double)s_bce[0] / count;
            const unsigned long long P = g_pen;
            const unsigned long long C = g_cnt;
            const double border = (P == 0) ? 0.0
                                : (double)P / (double)(C ? C : 1ull);
            out[0] = (float)(bce_mean + sqrt(border));
            g_pen = 0; g_cnt = 0; g_done = 0;   // restore for next graph replay
        }
    }
}

extern "C" void kernel_launch(void* const* d_in, const int* in_sizes, int n_in,
                              void* d_out, int out_size) {
    const float* pred = (const float*)d_in[0];
    const float* targ = (const float*)d_in[1];
    const long long total = in_sizes[0];
    const int N = (int)(total / ((long long)HDIM * WDIM));   // 32

    dim3 grid(WDIM / CB, N);   // (64, 32) = 2048 blocks
    dtl_main<<<grid, NTHREADS>>>(pred, targ, (float*)d_out);
}

// round 13
// speedup vs baseline: 1.1184x; 1.1184x over previous
#include <cuda_runtime.h>
#include <math.h>

// Shape fixed by dataset: (N=32, C=1, H=1024, W=1024) f32.
#define HDIM 1024
#define WDIM 1024
#define W4   (WDIM / 4)        // 256 float4 per row
#define C4   8                 // float4-columns per block (R3 geometry: 128B/row/warp)
#define CB   (C4 * 4)          // 32 scalar columns per block
#define NWORDS (HDIM / 32)     // 32 words per column
#define NTHREADS 256
#define MAXBLK 2048

__device__ unsigned long long g_pen;
__device__ unsigned long long g_cnt;
__device__ float              g_bce[MAXBLK];
__device__ unsigned int       g_done;

__global__ __launch_bounds__(NTHREADS, 6)
void dtl_main(const float* __restrict__ pred, const float* __restrict__ targ,
              float* __restrict__ out) {
    __shared__ unsigned int mask[NWORDS][CB + 1];   // [word][col]
    __shared__ float        s_bce[NTHREADS];
    __shared__ unsigned int s_pen[NTHREADS];
    __shared__ unsigned int s_cnt[NTHREADS];
    __shared__ bool         s_last;

    const int tid = threadIdx.x;
    const int c   = tid & (C4 - 1);      // float4 column 0..7
    const int r   = tid >> 3;            // word index 0..31
    const int n   = blockIdx.y;
    const int cb  = c * 4;
    const int i0  = r * 32;

    const float4* t4 = (const float4*)(targ + (size_t)n * HDIM * WDIM)
                       + blockIdx.x * C4 + c;
    const float4* p4 = (const float4*)(pred + (size_t)n * HDIM * WDIM)
                       + blockIdx.x * C4 + c;

    // ---- Phase 1: build mask words via exact FFMA bit-packing ----
    {
        float lo0 = 0.f, lo1 = 0.f, lo2 = 0.f, lo3 = 0.f;
        float hi0 = 0.f, hi1 = 0.f, hi2 = 0.f, hi3 = 0.f;
        const float4* tp = t4 + (size_t)i0 * W4;
        #pragma unroll
        for (int b = 0; b < 16; ++b) {
            float4 t = __ldcs(tp); tp += W4;
            const float s = (float)(1u << b);
            lo0 += t.x * s; lo1 += t.y * s; lo2 += t.z * s; lo3 += t.w * s;
        }
        #pragma unroll
        for (int b = 0; b < 16; ++b) {
            float4 t = __ldcs(tp); tp += W4;
            const float s = (float)(1u << b);
            hi0 += t.x * s; hi1 += t.y * s; hi2 += t.z * s; hi3 += t.w * s;
        }
        mask[r][cb + 0] = (unsigned)lo0 | ((unsigned)hi0 << 16);
        mask[r][cb + 1] = (unsigned)lo1 | ((unsigned)hi1 << 16);
        mask[r][cb + 2] = (unsigned)lo2 | ((unsigned)hi2 << 16);
        mask[r][cb + 3] = (unsigned)lo3 | ((unsigned)hi3 << 16);
    }
    __syncthreads();

    // ---- Per-column boundary state (once per thread) ----
    unsigned mw[4], rm[4];
    int prevOut[4], nextOut[4];
    #pragma unroll
    for (int j = 0; j < 4; ++j) {
        mw[j] = mask[r][cb + j];
        rm[j] = __brev(mw[j]);
        int p = -(1 << 20);
        for (int wd = r - 1; wd >= 0; --wd) {
            unsigned m = mask[wd][cb + j];
            if (m) { p = wd * 32 + 31 - __clz(m); break; }
        }
        prevOut[j] = p;
        int na = 1 << 20;
        for (int wd = r + 1; wd < NWORDS; ++wd) {
            unsigned m = mask[wd][cb + j];
            if (m) { na = wd * 32 + __ffs(m) - 1; break; }
        }
        nextOut[j] = na;
    }

    // ---- Phase 2: stream predictions; fully branchless dist + accumulate ----
    float bce = 0.0f;
    unsigned int pc = 0;                 // (pen << 8) | cnt packed accumulator
    {
        const float4* pp = p4 + (size_t)i0 * W4;
        #pragma unroll 8
        for (int b = 0; b < 32; ++b) {
            const int i = i0 + b;
            float4 p = __ldcs(pp); pp += W4;
            const float pv[4] = {p.x, p.y, p.z, p.w};
            // masks shared across the 4 columns of this row
            const unsigned loMask = (2u << b) - 1u;        // bits <= b
            const unsigned hiMaskR = 0xFFFFFFFFu >> b;     // reversed-mask bits for >= b
            float e[4];
            #pragma unroll
            for (int j = 0; j < 4; ++j) {
                const float v = pv[j];
                const unsigned y = mw[j] & loMask;
                const unsigned z = rm[j] & hiMaskR;
                // pd: distance up to nearest target (0 if this row is a target)
                const int pd = y ? (b - 31 + __clz(y)) : (i - prevOut[j]);
                // nd: distance down to nearest target (0 if this row is a target)
                const int nd = z ? (__clz(z) - b) : (nextOut[j] - i);
                const int dist = min(min(pd, nd), HDIM);
                // dist == 0  <=>  target bit set
                bce += fmaxf(v, 0.0f);
                if (dist == 0) bce -= v;
                if (v > 0.0f && dist > 0) pc += ((unsigned)dist << 8) + 1u;
                e[j] = __expf(-fabsf(v));
            }
            // log batching: product of (1+e_j) in (1,16] -> one LG2
            bce += __logf(((1.0f + e[0]) * (1.0f + e[1]))
                        * ((1.0f + e[2]) * (1.0f + e[3])));
        }
    }

    // ---- Block reduction (deterministic tree) ----
    s_bce[tid] = bce; s_pen[tid] = pc >> 8; s_cnt[tid] = pc & 0xFFu;
    __syncthreads();
    for (int s = NTHREADS / 2; s > 0; s >>= 1) {
        if (tid < s) {
            s_bce[tid] += s_bce[tid + s];
            s_pen[tid] += s_pen[tid + s];
            s_cnt[tid] += s_cnt[tid + s];
        }
        __syncthreads();
    }

    const int nblk = gridDim.x * gridDim.y;
    if (tid == 0) {
        const int blk = blockIdx.y * gridDim.x + blockIdx.x;
        g_bce[blk] = s_bce[0];
        atomicAdd(&g_pen, (unsigned long long)s_pen[0]);
        atomicAdd(&g_cnt, (unsigned long long)s_cnt[0]);
        __threadfence();
        unsigned int ticket = atomicAdd(&g_done, 1u);
        s_last = (ticket == (unsigned)(nblk - 1));
    }
    __syncthreads();

    // ---- Last block finalizes (fixed-order sums -> deterministic) ----
    if (s_last) {
        __threadfence();
        float acc = 0.0f;
        for (int i = tid; i < nblk; i += NTHREADS) acc += g_bce[i];
        s_bce[tid] = acc;
        __syncthreads();
        for (int s = NTHREADS / 2; s > 0; s >>= 1) {
            if (tid < s) s_bce[tid] += s_bce[tid + s];
            __syncthreads();
        }
        if (tid == 0) {
            const double count = (double)gridDim.y * HDIM * WDIM;
            const double bce_mean = (double)s_bce[0] / count;
            const unsigned long long P = g_pen;
            const unsigned long long C = g_cnt;
            const double border = (P == 0) ? 0.0
                                : (double)P / (double)(C ? C : 1ull);
            out[0] = (float)(bce_mean + sqrt(border));
            g_pen = 0; g_cnt = 0; g_done = 0;   // restore for next graph replay
        }
    }
}

extern "C" void kernel_launch(void* const* d_in, const int* in_sizes, int n_in,
                              void* d_out, int out_size) {
    const float* pred = (const float*)d_in[0];
    const float* targ = (const float*)d_in[1];
    const long long total = in_sizes[0];
    const int N = (int)(total / ((long long)HDIM * WDIM));   // 32

    dim3 grid(WDIM / CB, N);   // (32, 32) = 1024 blocks
    dtl_main<<<grid, NTHREADS>>>(pred, targ, (float*)d_out);
}